// round 4
// baseline (speedup 1.0000x reference)
#include <cuda_runtime.h>
#include <math_constants.h>

#define NSEG 8192
#define D    128
#define CAP  208      // max rows cached in SMEM per segment (mean ~122, std ~11)
#define NTHR 256

// SMEM: xs[CAP*D] + gv[CAP] + red[64]
static const int SMEM_BYTES = (CAP * D + CAP + 64) * 4;

__device__ int g_seg_start[NSEG + 1];
__device__ int g_is_i64;

// Detect int64 vs int32 batch: if int64, every odd 32-bit word (high word of a
// small non-negative value) is zero. If int32, odd words are batch[1],batch[3],...
// which reach segment >=1 well within the first 2048 words.
__global__ void probe_kernel(const int* __restrict__ raw, int n) {
    int w = 1 + 2 * (int)threadIdx.x;           // 1024 threads -> words 1..2047
    int v = (w < n) ? raw[w] : 0;
    int any = __syncthreads_or(v != 0);
    if (threadIdx.x == 0) g_is_i64 = any ? 0 : 1;
}

__global__ void bounds_kernel(const void* __restrict__ braw, int n) {
    int i = blockIdx.x * blockDim.x + threadIdx.x;
    if (i >= n) return;
    const int* b32 = (const int*)braw;
    const long long* b64 = (const long long*)braw;
    bool i64 = (g_is_i64 != 0);
    int bi = i64 ? (int)b64[i] : b32[i];
    int bp = (i == 0) ? -1 : (i64 ? (int)b64[i - 1] : b32[i - 1]);
    for (int s = bp + 1; s <= bi; ++s) g_seg_start[s] = i;
    if (i == n - 1)
        for (int s = bi + 1; s <= NSEG; ++s) g_seg_start[s] = n;
}

__global__ __launch_bounds__(NTHR, 2)
void seg_kernel(const float* __restrict__ x, const float* __restrict__ W,
                const float* __restrict__ bias,
                float* __restrict__ out, float* __restrict__ attn)
{
    extern __shared__ float sm[];
    float* xs  = sm;                 // [CAP * D]
    float* gv  = sm + CAP * D;       // [CAP]   gate -> e -> attn weight
    float* red = gv + CAP;           // [64]    reduction scratch

    const int s     = blockIdx.x;
    const int start = g_seg_start[s];
    const int count = g_seg_start[s + 1] - start;
    const int tid   = threadIdx.x;
    const int lane  = tid & 31;
    const int wid   = tid >> 5;

    if (count == 0) {
        if (tid < D) out[(size_t)s * D + tid] = 0.0f;   // d_out is poisoned
        return;
    }

    // W (512B) broadcast-loaded per warp; hits L1 after first warp.
    const float4 w4 = __ldg(&((const float4*)W)[lane]);
    const float  b0 = __ldg(bias);

    const float4* src = (const float4*)(x + (size_t)start * D);
    float4*       dst = (float4*)xs;

    // ---- Fused: stream rows gmem->smem AND compute gate per row ----
    // i = tid + k*NTHR: each warp covers exactly one 32-float4 row per iter
    // (rows are warp-uniform since NTHR and tot are multiples of 32).
    float wmax = -CUDART_INF_F;
    const int tot = count * 32;
    #pragma unroll 4
    for (int i = tid; i < tot; i += NTHR) {
        float4 v = src[i];
        int r = i >> 5;
        if (r < CAP) dst[i] = v;
        float p = v.x * w4.x + v.y * w4.y + v.z * w4.z + v.w * w4.w;
        #pragma unroll
        for (int o = 16; o > 0; o >>= 1) p += __shfl_xor_sync(0xFFFFFFFFu, p, o);
        float g = p + b0;                     // identical on all lanes
        if (lane == 0) {
            if (r < CAP) gv[r] = g;
            else         attn[start + r] = g; // overflow: gate scratch in gmem
        }
        wmax = fmaxf(wmax, g);
    }
    #pragma unroll
    for (int o = 16; o > 0; o >>= 1)
        wmax = fmaxf(wmax, __shfl_xor_sync(0xFFFFFFFFu, wmax, o));
    if (lane == 0) red[wid] = wmax;
    __syncthreads();
    if (tid == 0) {
        float m = red[0];
        #pragma unroll
        for (int k = 1; k < 8; k++) m = fmaxf(m, red[k]);
        red[32] = m;
    }
    __syncthreads();
    const float gmax = red[32];

    // ---- exp + segment sum ----
    float ls = 0.0f;
    for (int r = tid; r < count; r += NTHR) {
        float g = (r < CAP) ? gv[r] : attn[start + r];
        float e = expf(g - gmax);
        if (r < CAP) gv[r] = e; else attn[start + r] = e;
        ls += e;
    }
    #pragma unroll
    for (int o = 16; o > 0; o >>= 1) ls += __shfl_xor_sync(0xFFFFFFFFu, ls, o);
    if (lane == 0) red[8 + wid] = ls;
    __syncthreads();
    if (tid == 0) {
        float dsum = 0.0f;
        #pragma unroll
        for (int k = 0; k < 8; k++) dsum += red[8 + k];
        red[33] = 1.0f / (dsum + 1e-16f);
    }
    __syncthreads();
    const float inv = red[33];

    // ---- finalize attn weights ----
    for (int r = tid; r < count; r += NTHR) {
        float e = (r < CAP) ? gv[r] : attn[start + r];
        float a = e * inv;
        attn[start + r] = a;
        if (r < CAP) gv[r] = a;
    }
    __syncthreads();

    // ---- attn-weighted ReLU pooling from SMEM ----
    const int d    = tid & (D - 1);
    const int half = tid >> 7;                // two row-phases in parallel
    float acc = 0.0f;
    for (int r = half; r < count; r += 2) {
        float a  = (r < CAP) ? gv[r] : attn[start + r];
        float xv = (r < CAP) ? xs[r * D + d]
                             : __ldg(&x[(size_t)(start + r) * D + d]);
        acc = fmaf(a, fmaxf(xv, 0.0f), acc);
    }
    __syncthreads();                          // done reading gv; reuse as buffer
    if (half == 1) gv[d] = acc;
    __syncthreads();
    if (half == 0) out[(size_t)s * D + d] = acc + gv[d];
}

extern "C" void kernel_launch(void* const* d_in, const int* in_sizes, int n_in,
                              void* d_out, int out_size) {
    const float* x     = (const float*)d_in[0];
    const void*  batch = d_in[1];
    const float* W     = (const float*)d_in[2];
    const float* b     = (const float*)d_in[3];
    const int    n     = in_sizes[1];   // batch element count = N

    float* out  = (float*)d_out;                   // [NSEG, D]
    float* attn = out + (size_t)NSEG * D;          // [N, 1] follows in tuple order

    probe_kernel<<<1, 1024>>>((const int*)batch, n);
    bounds_kernel<<<(n + 255) / 256, 256>>>(batch, n);
    cudaFuncSetAttribute(seg_kernel,
                         cudaFuncAttributeMaxDynamicSharedMemorySize, SMEM_BYTES);
    seg_kernel<<<NSEG, NTHR, SMEM_BYTES>>>(x, W, b, out, attn);
}

// round 6
// speedup vs baseline: 1.9224x; 1.9224x over previous
#include <cuda_runtime.h>
#include <math_constants.h>

#define NSEG 8192
#define D    128
#define CAP  208      // max rows cached in SMEM per segment (mean ~122, sd ~11)
#define NTHR 256

// dynamic SMEM: xs[CAP*D] + gv[CAP] + red[64]
static const int SMEM_BYTES = (CAP * D + CAP + 64) * 4;

__device__ int g_seg_start[NSEG + 1];
__device__ int g_is_i64;

// Detect int64 vs int32 batch: sorted small non-negative values -> if int64,
// every odd 32-bit word (high half) is zero within the first 2048 words.
__global__ void probe_kernel(const int* __restrict__ raw, int n) {
    int w = 1 + 2 * (int)threadIdx.x;
    int v = (w < n) ? raw[w] : 0;
    int any = __syncthreads_or(v != 0);
    if (threadIdx.x == 0) g_is_i64 = any ? 0 : 1;
}

__global__ void bounds_kernel(const void* __restrict__ braw, int n) {
    int i = blockIdx.x * blockDim.x + threadIdx.x;
    if (i >= n) return;
    const int* b32 = (const int*)braw;
    const long long* b64 = (const long long*)braw;
    bool i64 = (g_is_i64 != 0);
    int bi = i64 ? (int)b64[i] : b32[i];
    int bp = (i == 0) ? -1 : (i64 ? (int)b64[i - 1] : b32[i - 1]);
    for (int s = bp + 1; s <= bi; ++s) g_seg_start[s] = i;
    if (i == n - 1)
        for (int s = bi + 1; s <= NSEG; ++s) g_seg_start[s] = n;
}

__device__ __forceinline__ float warp_add(float v) {
    #pragma unroll
    for (int o = 16; o > 0; o >>= 1) v += __shfl_xor_sync(0xFFFFFFFFu, v, o);
    return v;
}
__device__ __forceinline__ float warp_max(float v) {
    #pragma unroll
    for (int o = 16; o > 0; o >>= 1)
        v = fmaxf(v, __shfl_xor_sync(0xFFFFFFFFu, v, o));
    return v;
}

__global__ __launch_bounds__(NTHR, 2)
void seg_kernel(const float* __restrict__ x, const float* __restrict__ W,
                const float* __restrict__ bias,
                float* __restrict__ out, float* __restrict__ attn)
{
    extern __shared__ float sm[];
    __shared__ unsigned long long mbar;     // 8B-aligned static smem
    float* xs  = sm;                        // [CAP * D]
    float* gv  = sm + CAP * D;              // [CAP]   gate -> e -> attn weight
    float* red = gv + CAP;                  // [64]

    const int s     = blockIdx.x;
    const int start = g_seg_start[s];
    const int count = g_seg_start[s + 1] - start;
    const int tid   = threadIdx.x;
    const int lane  = tid & 31;
    const int wid   = tid >> 5;

    if (count == 0) {
        if (tid < D) out[(size_t)s * D + tid] = 0.0f;   // d_out is poisoned
        return;
    }

    const int      cached = (count < CAP) ? count : CAP;
    const unsigned cbytes = (unsigned)cached * (D * 4);
    const unsigned bar    = (unsigned)__cvta_generic_to_shared(&mbar);
    const unsigned dst    = (unsigned)__cvta_generic_to_shared(xs);
    const float*   src    = x + (size_t)start * D;

    if (tid == 0)
        asm volatile("mbarrier.init.shared.b64 [%0], 1;" :: "r"(bar) : "memory");
    __syncthreads();
    if (tid == 0) {
        asm volatile("mbarrier.arrive.expect_tx.shared.b64 _, [%0], %1;"
                     :: "r"(bar), "r"(cbytes) : "memory");
        asm volatile(
            "cp.async.bulk.shared::cta.global.mbarrier::complete_tx::bytes "
            "[%0], [%1], %2, [%3];"
            :: "r"(dst), "l"(src), "r"(cbytes), "r"(bar) : "memory");
    }

    // ---- while TMA is in flight: load W, handle rare overflow rows ----
    const float4 w4 = __ldg(&((const float4*)W)[lane]);
    const float  b0 = __ldg(bias);

    float wmax = -CUDART_INF_F;
    for (int r = CAP + wid; r < count; r += 8) {       // warp-per-row, from gmem
        float4 v = __ldg(&((const float4*)(x + (size_t)(start + r) * D))[lane]);
        float p = v.x * w4.x + v.y * w4.y + v.z * w4.z + v.w * w4.w;
        float g = warp_add(p) + b0;
        if (lane == 0) attn[start + r] = g;            // gate scratch in gmem
        wmax = fmaxf(wmax, g);
    }

    // ---- wait for segment tile ----
    asm volatile(
        "{\n\t.reg .pred p;\n"
        "LWAIT%=:\n\t"
        "mbarrier.try_wait.parity.acquire.cta.shared::cta.b64 p, [%0], 0, 0x989680;\n\t"
        "@p bra LDONE%=;\n\t"
        "bra LWAIT%=;\n"
        "LDONE%=:\n\t}"
        :: "r"(bar) : "memory");

    // ---- gate pass from SMEM: warp-per-row ----
    const float4* xs4 = (const float4*)xs;
    for (int r = wid; r < cached; r += 8) {
        float4 v = xs4[r * 32 + lane];                 // conflict-free LDS.128
        float p = v.x * w4.x + v.y * w4.y + v.z * w4.z + v.w * w4.w;
        float g = warp_add(p) + b0;
        if (lane == 0) gv[r] = g;
        wmax = fmaxf(wmax, g);
    }
    wmax = warp_max(wmax);
    if (lane == 0) red[wid] = wmax;
    __syncthreads();
    if (tid == 0) {
        float m = red[0];
        #pragma unroll
        for (int k = 1; k < 8; k++) m = fmaxf(m, red[k]);
        red[32] = m;
    }
    __syncthreads();
    const float gmax = red[32];

    // ---- exp + segment sum ----
    float ls = 0.0f;
    for (int r = tid; r < count; r += NTHR) {
        float g = (r < CAP) ? gv[r] : attn[start + r];
        float e = __expf(g - gmax);
        if (r < CAP) gv[r] = e; else attn[start + r] = e;
        ls += e;
    }
    ls = warp_add(ls);
    if (lane == 0) red[8 + wid] = ls;
    __syncthreads();
    if (tid == 0) {
        float dsum = 0.0f;
        #pragma unroll
        for (int k = 0; k < 8; k++) dsum += red[8 + k];
        red[33] = 1.0f / (dsum + 1e-16f);
    }
    __syncthreads();
    const float inv = red[33];

    // ---- finalize attn weights ----
    for (int r = tid; r < count; r += NTHR) {
        float e = (r < CAP) ? gv[r] : attn[start + r];
        float a = e * inv;
        attn[start + r] = a;
        if (r < CAP) gv[r] = a;
    }
    __syncthreads();

    // ---- attn-weighted ReLU pooling from SMEM ----
    const int d    = tid & (D - 1);
    const int half = tid >> 7;                 // two row-phases in parallel
    float acc = 0.0f;
    for (int r = half; r < count; r += 2) {
        float a  = (r < CAP) ? gv[r] : attn[start + r];
        float xv = (r < CAP) ? xs[r * D + d]
                             : __ldg(&x[(size_t)(start + r) * D + d]);
        acc = fmaf(a, fmaxf(xv, 0.0f), acc);
    }
    __syncthreads();                           // done reading gv; reuse as buffer
    if (half == 1) gv[d] = acc;
    __syncthreads();
    if (half == 0) out[(size_t)s * D + d] = acc + gv[d];
}

extern "C" void kernel_launch(void* const* d_in, const int* in_sizes, int n_in,
                              void* d_out, int out_size) {
    const float* x     = (const float*)d_in[0];
    const void*  batch = d_in[1];
    const float* W     = (const float*)d_in[2];
    const float* b     = (const float*)d_in[3];
    const int    n     = in_sizes[1];          // batch element count = N

    float* out  = (float*)d_out;               // [NSEG, D]
    float* attn = out + (size_t)NSEG * D;      // [N, 1] follows in tuple order

    probe_kernel<<<1, 1024>>>((const int*)batch, n);
    bounds_kernel<<<(n + 255) / 256, 256>>>(batch, n);
    cudaFuncSetAttribute(seg_kernel,
                         cudaFuncAttributeMaxDynamicSharedMemorySize, SMEM_BYTES);
    seg_kernel<<<NSEG, NTHR, SMEM_BYTES>>>(x, W, b, out, attn);
}